// round 4
// baseline (speedup 1.0000x reference)
#include <cuda_runtime.h>
#include <cstdint>

#define ALPHA 0.1f
#define BETA  0.1f
#define B_  10
#define K_  16
#define NP_ 192
#define N_  3072
#define FD_ 70

// colfac[b][p][j] = (memb[b][j]==p) ? 1 : ratio[b][p][memb[b][j]]
__device__ __align__(16) float g_colfac[B_ * K_ * N_];

// ---------------------------------------------------------------------------
// packed f32x2 helpers (Blackwell FFMA2 — PTX-only path)
// ---------------------------------------------------------------------------
__device__ __forceinline__ unsigned long long pack2(float x, float y) {
    unsigned long long r;
    asm("mov.b64 %0, {%1, %2};" : "=l"(r) : "f"(x), "f"(y));
    return r;
}
__device__ __forceinline__ unsigned long long ffma2(unsigned long long a,
                                                    unsigned long long b,
                                                    unsigned long long c) {
    unsigned long long d;
    asm("fma.rn.f32x2 %0, %1, %2, %3;" : "=l"(d) : "l"(a), "l"(b), "l"(c));
    return d;
}
__device__ __forceinline__ float2 unpack2(unsigned long long v) {
    float2 r;
    asm("mov.b64 {%0, %1}, %2;" : "=f"(r.x), "=f"(r.y) : "l"(v));
    return r;
}

// ---------------------------------------------------------------------------
// Kernel 1: per-batch ratio + colfac table  (10 blocks x 256 threads)
// ---------------------------------------------------------------------------
__global__ void k_setup(const float* __restrict__ Hc,
                        const float* __restrict__ Rc,
                        const float* __restrict__ rcs,
                        const int*   __restrict__ memb) {
    __shared__ float HcS[256], RcS[256], rS[16], SS[16], ratioS[256];
    const int b = blockIdx.x;
    const int t = threadIdx.x;

    HcS[t] = Hc[b * 256 + t];
    RcS[t] = Rc[b * 256 + t];
    __syncthreads();

    if (t < 16) {            // column sums of Hc
        float s = 0.f;
        #pragma unroll
        for (int i = 0; i < 16; i++) s += HcS[i * 16 + t];
        SS[t] = s;
    }
    __syncthreads();

    if (t < 16) {            // del_diag[k]/rcs_diag[k,k]
        float d = 0.f;
        #pragma unroll
        for (int j = 0; j < 16; j++) d += SS[j] * RcS[j * 16 + t];
        rS[t] = ALPHA * d / rcs[b * 256 + t * 16 + t];
    }
    __syncthreads();

    {   // ratio[i][j] = 1 + r[j] + Rc[j][i]*r[i]/Rc[i][j]
        int i = t >> 4, j = t & 15;
        ratioS[t] = 1.0f + rS[j] + RcS[j * 16 + i] * rS[i] / RcS[t];
    }
    __syncthreads();

    for (int idx = t; idx < K_ * N_; idx += 256) {
        int p = idx / N_;
        int j = idx - p * N_;
        int mq = memb[b * N_ + j];
        g_colfac[b * (K_ * N_) + idx] = (mq == p) ? 1.0f : ratioS[(p << 4) + mq];
    }
}

// ---------------------------------------------------------------------------
// Kernel 2: Hp_k = BETA * diag(dis) * (Wp.*Rn) * diag(dis) * Hp * theta
// one block per (b,k): 160 blocks x 384 threads.
// thread = (row m in 0..191, g-half in {0,1}); packed f32x2 accumulators.
// ---------------------------------------------------------------------------
#define HP_PAD 71
#define C1_PAD 72
#define AS_PAD 33
#define SMEM_FLOATS (NP_ * HP_PAD + NP_ * C1_PAD + FD_ * FD_ + NP_)
#define SMEM_BYTES  (SMEM_FLOATS * 4)

__global__ __launch_bounds__(384, 1)
void k_hpk(const float* __restrict__ Wp,
           const float* __restrict__ Rn,
           const float* __restrict__ Hp,
           const float* __restrict__ deg,
           const float* __restrict__ theta,
           float* __restrict__ outH) {
    extern __shared__ float sm[];
    float* HpS  = sm;                         // [192][71], reused as AsS [192][33]
    float* AsS  = sm;
    float* C1s  = sm + NP_ * HP_PAD;          // [192][72]
    float* thS  = C1s + NP_ * C1_PAD;         // [70*70]
    float* disS = thS + FD_ * FD_;            // [192]

    const int bk = blockIdx.x;
    const int t  = threadIdx.x;
    const float* Hp_b = Hp + (size_t)bk * NP_ * FD_;
    const float* Wp_b = Wp + (size_t)bk * NP_ * NP_;
    const float* Rn_b = Rn + (size_t)bk * NP_ * NP_;

    for (int i = t; i < NP_; i += 384) disS[i] = rsqrtf(deg[bk * NP_ + i]);
    for (int i = t; i < FD_ * FD_; i += 384) thS[i] = theta[i];
    __syncthreads();
    // HpS[m][f] = dis[m] * Hp[m][f]
    for (int idx = t; idx < NP_ * FD_; idx += 384) {
        int m = idx / FD_;
        HpS[m * HP_PAD + (idx - m * FD_)] = Hp_b[idx] * disS[m];
    }
    __syncthreads();

    const int m    = t % NP_;        // output row (and C1 row in phase A)
    const int half = t / NP_;        // g-half
    const int gp0  = half ? 17 : 0;  // first g-pair (overlap pair 17: benign dup)

    unsigned long long acc[18];
    #pragma unroll
    for (int i = 0; i < 18; i++) acc[i] = 0ULL;

    // Phase A: C1[m][g] = sum_f HpS[m][f] * theta[f][g]
    for (int f = 0; f < FD_; f++) {
        float hp = HpS[m * HP_PAD + f];
        unsigned long long hp2 = pack2(hp, hp);
        const unsigned long long* th2 =
            (const unsigned long long*)(thS + f * FD_) + gp0;
        #pragma unroll
        for (int i = 0; i < 18; i++) acc[i] = ffma2(hp2, th2[i], acc[i]);
    }
    {
        unsigned long long* c2 = (unsigned long long*)(C1s + m * C1_PAD) + gp0;
        #pragma unroll
        for (int i = 0; i < 18; i++) c2[i] = acc[i];
    }
    __syncthreads();

    // Phase B: out[m][g] = sum_mm (Wp.*Rn)[m][mm] * C1[mm][g]
    #pragma unroll
    for (int i = 0; i < 18; i++) acc[i] = 0ULL;

    for (int mc = 0; mc < NP_; mc += 32) {
        for (int idx = t; idx < NP_ * 32; idx += 384) {
            int n = idx >> 5, mm = idx & 31;
            AsS[n * AS_PAD + mm] = Wp_b[n * NP_ + mc + mm] * Rn_b[n * NP_ + mc + mm];
        }
        __syncthreads();
        #pragma unroll 4
        for (int mm = 0; mm < 32; mm++) {
            float a = AsS[m * AS_PAD + mm];
            unsigned long long a2 = pack2(a, a);
            const unsigned long long* c2 =
                (const unsigned long long*)(C1s + (mc + mm) * C1_PAD) + gp0;
            #pragma unroll
            for (int i = 0; i < 18; i++) acc[i] = ffma2(a2, c2[i], acc[i]);
        }
        __syncthreads();   // protect AsS for next stage / C1s for epilogue
    }

    // Epilogue: scale, round-trip through smem for coalesced global stores
    {
        float scale = BETA * disS[m];
        unsigned long long* crow = (unsigned long long*)(C1s + m * C1_PAD) + gp0;
        #pragma unroll
        for (int i = 0; i < 18; i++) {
            float2 v = unpack2(acc[i]);
            v.x *= scale; v.y *= scale;
            crow[i] = pack2(v.x, v.y);
        }
    }
    __syncthreads();
    float* outp = outH + (size_t)bk * NP_ * FD_;
    for (int idx = t; idx < NP_ * FD_; idx += 384) {
        int mm = idx / FD_;
        outp[idx] = C1s[mm * C1_PAD + (idx - mm * FD_)];
    }
}

// ---------------------------------------------------------------------------
// Kernel 3: W_out = W * colfac[b][memb[i]][:]   (pure HBM stream)
// one block per (b,row): 30720 blocks x 256 threads, 3 float4 per thread
// ---------------------------------------------------------------------------
__global__ __launch_bounds__(256)
void k_wscale(const float* __restrict__ W,
              const int*   __restrict__ memb,
              float* __restrict__ outW) {
    const int bid = blockIdx.x;
    const int b   = bid / N_;
    const int i   = bid - b * N_;
    const int mi  = __ldg(&memb[b * N_ + i]);

    const float4* w  = (const float4*)(W + (size_t)bid * N_);
    const float4* cf = (const float4*)(g_colfac + (size_t)(b * K_ + mi) * N_);
    float4*       o  = (float4*)(outW + (size_t)bid * N_);

    const int t = threadIdx.x;
    float4 w0 = __ldcs(w + t);
    float4 w1 = __ldcs(w + t + 256);
    float4 w2 = __ldcs(w + t + 512);
    float4 c0 = __ldg(cf + t);
    float4 c1 = __ldg(cf + t + 256);
    float4 c2 = __ldg(cf + t + 512);

    float4 r0 = make_float4(w0.x * c0.x, w0.y * c0.y, w0.z * c0.z, w0.w * c0.w);
    float4 r1 = make_float4(w1.x * c1.x, w1.y * c1.y, w1.z * c1.z, w1.w * c1.w);
    float4 r2 = make_float4(w2.x * c2.x, w2.y * c2.y, w2.z * c2.z, w2.w * c2.w);

    __stcs(o + t,       r0);
    __stcs(o + t + 256, r1);
    __stcs(o + t + 512, r2);
}

// ---------------------------------------------------------------------------
extern "C" void kernel_launch(void* const* d_in, const int* in_sizes, int n_in,
                              void* d_out, int out_size) {
    const float* Hc    = (const float*)d_in[0];
    const float* Rc    = (const float*)d_in[1];
    const float* rcs   = (const float*)d_in[2];
    const float* Wp    = (const float*)d_in[3];
    const float* Rn    = (const float*)d_in[4];
    const float* Hp    = (const float*)d_in[5];
    const float* deg   = (const float*)d_in[6];
    const float* W     = (const float*)d_in[7];
    const float* theta = (const float*)d_in[8];
    const int*   memb  = (const int*)d_in[9];

    float* out  = (float*)d_out;
    float* outW = out;                                   // (B, N, N)
    float* outH = out + (size_t)B_ * N_ * N_;            // (B, K, NP, FD)

    cudaFuncSetAttribute(k_hpk, cudaFuncAttributeMaxDynamicSharedMemorySize,
                         SMEM_BYTES);

    k_setup<<<B_, 256>>>(Hc, Rc, rcs, memb);
    k_hpk<<<B_ * K_, 384, SMEM_BYTES>>>(Wp, Rn, Hp, deg, theta, outH);
    k_wscale<<<B_ * N_, 256>>>(W, memb, outW);
}

// round 10
// speedup vs baseline: 1.2081x; 1.2081x over previous
#include <cuda_runtime.h>
#include <cstdint>

#define ALPHA 0.1f
#define BETA  0.1f
#define B_  10
#define K_  16
#define NP_ 192
#define N_  3072
#define FD_ 70

// colfac[b][p][j] = (memb[b][j]==p) ? 1 : ratio[b][p][memb[b][j]]
__device__ __align__(16) float g_colfac[B_ * K_ * N_];

// ---------------------------------------------------------------------------
// packed f32x2 helpers (Blackwell FFMA2 — PTX-only path)
// ---------------------------------------------------------------------------
__device__ __forceinline__ unsigned long long pack2(float x, float y) {
    unsigned long long r;
    asm("mov.b64 %0, {%1, %2};" : "=l"(r) : "f"(x), "f"(y));
    return r;
}
__device__ __forceinline__ unsigned long long ffma2(unsigned long long a,
                                                    unsigned long long b,
                                                    unsigned long long c) {
    unsigned long long d;
    asm("fma.rn.f32x2 %0, %1, %2, %3;" : "=l"(d) : "l"(a), "l"(b), "l"(c));
    return d;
}

// ---------------------------------------------------------------------------
// Kernel 1: ratio + colfac. One block per (b,p): 160 blocks x 256 threads.
// Each block redundantly computes the 16x16 ratio (cheap) and fills one
// 3072-float colfac row with vectorized stores.
// ---------------------------------------------------------------------------
__global__ __launch_bounds__(256)
void k_setup(const float* __restrict__ Hc,
             const float* __restrict__ Rc,
             const float* __restrict__ rcs,
             const int*   __restrict__ memb) {
    __shared__ float HcS[256], RcS[256], rS[16], SS[16], ratioS[256];
    const int b = blockIdx.x >> 4;
    const int p = blockIdx.x & 15;
    const int t = threadIdx.x;

    HcS[t] = Hc[b * 256 + t];
    RcS[t] = Rc[b * 256 + t];
    __syncthreads();

    if (t < 16) {            // column sums of Hc
        float s = 0.f;
        #pragma unroll
        for (int i = 0; i < 16; i++) s += HcS[i * 16 + t];
        SS[t] = s;
    }
    __syncthreads();

    if (t < 16) {            // del_diag[k]/rcs_diag[k,k]
        float d = 0.f;
        #pragma unroll
        for (int j = 0; j < 16; j++) d += SS[j] * RcS[j * 16 + t];
        rS[t] = ALPHA * d / rcs[b * 256 + t * 16 + t];
    }
    __syncthreads();

    {   // ratio[i][j] = 1 + r[j] + Rc[j][i]*r[i]/Rc[i][j]
        int i = t >> 4, j = t & 15;
        ratioS[t] = 1.0f + rS[j] + RcS[j * 16 + i] * rS[i] / RcS[t];
    }
    __syncthreads();

    const int4* mb = (const int4*)(memb + b * N_);
    float4* cf = (float4*)(g_colfac + (size_t)(b * K_ + p) * N_);
    #pragma unroll
    for (int v = t; v < N_ / 4; v += 256) {      // 768 vec4, 3 iters
        int4 mq = mb[v];
        float4 r;
        r.x = (mq.x == p) ? 1.0f : ratioS[(p << 4) + mq.x];
        r.y = (mq.y == p) ? 1.0f : ratioS[(p << 4) + mq.y];
        r.z = (mq.z == p) ? 1.0f : ratioS[(p << 4) + mq.z];
        r.w = (mq.w == p) ? 1.0f : ratioS[(p << 4) + mq.w];
        cf[v] = r;
    }
}

// ---------------------------------------------------------------------------
// Kernel 2: Hp_k = BETA * diag(dis) * (Wp.*Rn) * diag(dis) * Hp * theta
// TWO blocks per (b,k) (g split in halves of 36 cols = 18 f32x2 pairs).
// grid = 320, block = 384, smem 94.6KB -> 2 CTAs/SM.
// thread = (row r in 0..63, pair-group pg in 0..5): handles rows {r,r+64,r+128}
// x 3 pairs -> broadcast c2/th2 loads amortized over 3 rows.
// ---------------------------------------------------------------------------
#define HP_PAD 71
#define C1_PAD 38
#define TH_W   36
#define AS_PAD 33
#define SMEM_FLOATS (NP_ * HP_PAD + NP_ * C1_PAD + FD_ * TH_W + NP_)
#define SMEM_BYTES  (SMEM_FLOATS * 4)

__global__ __launch_bounds__(384, 2)
void k_hpk(const float* __restrict__ Wp,
           const float* __restrict__ Rn,
           const float* __restrict__ Hp,
           const float* __restrict__ deg,
           const float* __restrict__ theta,
           float* __restrict__ outH) {
    extern __shared__ float sm[];
    float* HpS  = sm;                          // [192][71], aliased as AsS [192][33]
    float* AsS  = sm;
    float* C1s  = sm + NP_ * HP_PAD;           // [192][38] (36 used)
    float* thS  = C1s + NP_ * C1_PAD;          // [70][36]
    float* disS = thS + FD_ * TH_W;            // [192]

    const int bid = blockIdx.x;
    const int bk  = bid >> 1;
    const int g0  = (bid & 1) * TH_W;          // 0 or 36 (global col offset)
    const int t   = threadIdx.x;
    const float* Hp_b = Hp + (size_t)bk * NP_ * FD_;
    const float* Wp_b = Wp + (size_t)bk * NP_ * NP_;
    const float* Rn_b = Rn + (size_t)bk * NP_ * NP_;

    for (int i = t; i < NP_; i += 384) disS[i] = rsqrtf(deg[bk * NP_ + i]);
    // theta columns [g0, g0+36), zero-padded past col 69
    for (int idx = t; idx < FD_ * TH_W; idx += 384) {
        int f = idx / TH_W, c = idx - f * TH_W;
        int g = g0 + c;
        thS[idx] = (g < FD_) ? theta[f * FD_ + g] : 0.0f;
    }
    __syncthreads();
    // HpS[m][f] = dis[m] * Hp[m][f]
    for (int idx = t; idx < NP_ * FD_; idx += 384) {
        int m = idx / FD_;
        HpS[m * HP_PAD + (idx - m * FD_)] = Hp_b[idx] * disS[m];
    }
    __syncthreads();

    const int r  = t & 63;                     // base row
    const int lp = (t >> 6) * 3;               // local pair offset (0,3,..,15)

    unsigned long long acc[9];                 // [3 rows][3 pairs]
    #pragma unroll
    for (int i = 0; i < 9; i++) acc[i] = 0ULL;

    // Phase A: C1[m][g] = sum_f HpS[m][f] * theta[f][g]
    for (int f = 0; f < FD_; f++) {
        float h0 = HpS[ r         * HP_PAD + f];
        float h1 = HpS[(r +  64)  * HP_PAD + f];
        float h2 = HpS[(r + 128)  * HP_PAD + f];
        const unsigned long long* th2 =
            (const unsigned long long*)(thS + f * TH_W) + lp;
        unsigned long long t0 = th2[0], t1 = th2[1], t2 = th2[2];
        unsigned long long h02 = pack2(h0, h0);
        unsigned long long h12 = pack2(h1, h1);
        unsigned long long h22 = pack2(h2, h2);
        acc[0] = ffma2(h02, t0, acc[0]);
        acc[1] = ffma2(h02, t1, acc[1]);
        acc[2] = ffma2(h02, t2, acc[2]);
        acc[3] = ffma2(h12, t0, acc[3]);
        acc[4] = ffma2(h12, t1, acc[4]);
        acc[5] = ffma2(h12, t2, acc[5]);
        acc[6] = ffma2(h22, t0, acc[6]);
        acc[7] = ffma2(h22, t1, acc[7]);
        acc[8] = ffma2(h22, t2, acc[8]);
    }
    {
        unsigned long long* c0 = (unsigned long long*)(C1s +  r        * C1_PAD) + lp;
        unsigned long long* c1 = (unsigned long long*)(C1s + (r +  64) * C1_PAD) + lp;
        unsigned long long* c2 = (unsigned long long*)(C1s + (r + 128) * C1_PAD) + lp;
        c0[0] = acc[0]; c0[1] = acc[1]; c0[2] = acc[2];
        c1[0] = acc[3]; c1[1] = acc[4]; c1[2] = acc[5];
        c2[0] = acc[6]; c2[1] = acc[7]; c2[2] = acc[8];
    }
    __syncthreads();

    // Phase B: out[m][g] = sum_mm (Wp.*Rn)[m][mm] * C1[mm][g]
    #pragma unroll
    for (int i = 0; i < 9; i++) acc[i] = 0ULL;

    for (int mc = 0; mc < NP_; mc += 32) {
        for (int idx = t; idx < NP_ * 32; idx += 384) {
            int n = idx >> 5, mm = idx & 31;
            AsS[n * AS_PAD + mm] = Wp_b[n * NP_ + mc + mm] * Rn_b[n * NP_ + mc + mm];
        }
        __syncthreads();
        #pragma unroll 4
        for (int mm = 0; mm < 32; mm++) {
            float a0 = AsS[ r         * AS_PAD + mm];
            float a1 = AsS[(r +  64)  * AS_PAD + mm];
            float a2 = AsS[(r + 128)  * AS_PAD + mm];
            const unsigned long long* c2 =
                (const unsigned long long*)(C1s + (mc + mm) * C1_PAD) + lp;
            unsigned long long v0 = c2[0], v1 = c2[1], v2 = c2[2];
            unsigned long long a02 = pack2(a0, a0);
            unsigned long long a12 = pack2(a1, a1);
            unsigned long long a22 = pack2(a2, a2);
            acc[0] = ffma2(a02, v0, acc[0]);
            acc[1] = ffma2(a02, v1, acc[1]);
            acc[2] = ffma2(a02, v2, acc[2]);
            acc[3] = ffma2(a12, v0, acc[3]);
            acc[4] = ffma2(a12, v1, acc[4]);
            acc[5] = ffma2(a12, v2, acc[5]);
            acc[6] = ffma2(a22, v0, acc[6]);
            acc[7] = ffma2(a22, v1, acc[7]);
            acc[8] = ffma2(a22, v2, acc[8]);
        }
        __syncthreads();
    }

    // Epilogue: scale into C1s, then coalesced copy to global
    {
        float s0 = BETA * disS[r];
        float s1 = BETA * disS[r + 64];
        float s2 = BETA * disS[r + 128];
        unsigned long long sc0 = pack2(s0, s0);
        unsigned long long sc1 = pack2(s1, s1);
        unsigned long long sc2 = pack2(s2, s2);
        unsigned long long* c0 = (unsigned long long*)(C1s +  r        * C1_PAD) + lp;
        unsigned long long* c1 = (unsigned long long*)(C1s + (r +  64) * C1_PAD) + lp;
        unsigned long long* c2 = (unsigned long long*)(C1s + (r + 128) * C1_PAD) + lp;
        c0[0] = ffma2(sc0, acc[0], 0ULL);
        c0[1] = ffma2(sc0, acc[1], 0ULL);
        c0[2] = ffma2(sc0, acc[2], 0ULL);
        c1[0] = ffma2(sc1, acc[3], 0ULL);
        c1[1] = ffma2(sc1, acc[4], 0ULL);
        c1[2] = ffma2(sc1, acc[5], 0ULL);
        c2[0] = ffma2(sc2, acc[6], 0ULL);
        c2[1] = ffma2(sc2, acc[7], 0ULL);
        c2[2] = ffma2(sc2, acc[8], 0ULL);
    }
    __syncthreads();
    float* outp = outH + (size_t)bk * NP_ * FD_;
    for (int idx = t; idx < NP_ * TH_W; idx += 384) {
        int m = idx / TH_W, c = idx - m * TH_W;
        int g = g0 + c;
        if (g < FD_) outp[m * FD_ + g] = C1s[m * C1_PAD + c];
    }
}

// ---------------------------------------------------------------------------
// Kernel 3: W_out = W * colfac[b][memb[i]][:]   (pure HBM stream)
// one block per (b,row): 30720 blocks x 256 threads, 3 float4 per thread
// ---------------------------------------------------------------------------
__global__ __launch_bounds__(256)
void k_wscale(const float* __restrict__ W,
              const int*   __restrict__ memb,
              float* __restrict__ outW) {
    const int bid = blockIdx.x;
    const int b   = bid / N_;
    const int i   = bid - b * N_;
    const int mi  = __ldg(&memb[b * N_ + i]);

    const float4* w  = (const float4*)(W + (size_t)bid * N_);
    const float4* cf = (const float4*)(g_colfac + (size_t)(b * K_ + mi) * N_);
    float4*       o  = (float4*)(outW + (size_t)bid * N_);

    const int t = threadIdx.x;
    float4 w0 = __ldcs(w + t);
    float4 w1 = __ldcs(w + t + 256);
    float4 w2 = __ldcs(w + t + 512);
    float4 c0 = __ldg(cf + t);
    float4 c1 = __ldg(cf + t + 256);
    float4 c2 = __ldg(cf + t + 512);

    float4 r0 = make_float4(w0.x * c0.x, w0.y * c0.y, w0.z * c0.z, w0.w * c0.w);
    float4 r1 = make_float4(w1.x * c1.x, w1.y * c1.y, w1.z * c1.z, w1.w * c1.w);
    float4 r2 = make_float4(w2.x * c2.x, w2.y * c2.y, w2.z * c2.z, w2.w * c2.w);

    __stcs(o + t,       r0);
    __stcs(o + t + 256, r1);
    __stcs(o + t + 512, r2);
}

// ---------------------------------------------------------------------------
extern "C" void kernel_launch(void* const* d_in, const int* in_sizes, int n_in,
                              void* d_out, int out_size) {
    const float* Hc    = (const float*)d_in[0];
    const float* Rc    = (const float*)d_in[1];
    const float* rcs   = (const float*)d_in[2];
    const float* Wp    = (const float*)d_in[3];
    const float* Rn    = (const float*)d_in[4];
    const float* Hp    = (const float*)d_in[5];
    const float* deg   = (const float*)d_in[6];
    const float* W     = (const float*)d_in[7];
    const float* theta = (const float*)d_in[8];
    const int*   memb  = (const int*)d_in[9];

    float* out  = (float*)d_out;
    float* outW = out;                                   // (B, N, N)
    float* outH = out + (size_t)B_ * N_ * N_;            // (B, K, NP, FD)

    cudaFuncSetAttribute(k_hpk, cudaFuncAttributeMaxDynamicSharedMemorySize,
                         SMEM_BYTES);

    k_hpk<<<B_ * K_ * 2, 384, SMEM_BYTES>>>(Wp, Rn, Hp, deg, theta, outH);
    k_setup<<<B_ * K_, 256>>>(Hc, Rc, rcs, memb);
    k_wscale<<<B_ * N_, 256>>>(W, memb, outW);
}